// round 10
// baseline (speedup 1.0000x reference)
#include <cuda_runtime.h>
#include <cuda_fp16.h>
#include <cstdint>
#include <math.h>

#define NBATCH 4
#define SEQ    2048
#define DMODEL 512
#define DFFN   2048
#define BSTOT  (NBATCH*SEQ)

// ---------------- scratch ----------------
__device__ __align__(256) float g_x [BSTOT*DMODEL];
__device__ __align__(256) float g_v [BSTOT*DMODEL];
__device__ __align__(256) float g_at[BSTOT*DMODEL];
__device__ __align__(256) float g_r [BSTOT*DMODEL];
__device__ __align__(256) float g_f2[BSTOT*DMODEL];
__device__ __align__(256) float g_sc[(long long)NBATCH*SEQ*SEQ];
__device__ __align__(256) float g_pos[SEQ*DMODEL];
__device__ __align__(256) float g_bkq[2*DMODEL];
__device__ __align__(256) float g_sk[BSTOT];
__device__ __align__(256) float g_sq[BSTOT];

__device__ __align__(256) __half g_xh[BSTOT*DMODEL];
__device__ __align__(256) __half g_xl[BSTOT*DMODEL];
__device__ __align__(256) __half g_kqh[2*BSTOT*DMODEL];
__device__ __align__(256) __half g_kql[2*BSTOT*DMODEL];
__device__ __align__(256) __half g_vTh[BSTOT*DMODEL];
__device__ __align__(256) __half g_rh[BSTOT*DMODEL];
__device__ __align__(256) __half g_ph[(long long)NBATCH*SEQ*SEQ];
__device__ __align__(256) __half g_f1h[(long long)BSTOT*DFFN];
__device__ __align__(256) __half g_wkqTh[2*DMODEL*DMODEL];
__device__ __align__(256) __half g_wkqTl[2*DMODEL*DMODEL];
__device__ __align__(256) __half g_wvTh[DMODEL*DMODEL];
__device__ __align__(256) __half g_w1Th[DFFN*DMODEL];
__device__ __align__(256) __half g_w2Th[DMODEL*DFFN];
__device__ __align__(256) int8_t g_k8[(long long)BSTOT*2*DMODEL];   // [row, k8h|k8l]
__device__ __align__(256) int8_t g_q8[(long long)BSTOT*2*DMODEL];   // [row, q8l|q8h]

// ---------------- helpers ----------------
__device__ __forceinline__ uint32_t smem_u32(const void* p) {
    uint32_t a;
    asm("{ .reg .u64 t; cvta.to.shared.u64 t, %1; cvt.u32.u64 %0, t; }" : "=r"(a) : "l"(p));
    return a;
}
__device__ __forceinline__ void mmafp16(float c[4], const uint32_t a[4], uint32_t b0, uint32_t b1) {
    asm volatile(
        "mma.sync.aligned.m16n8k16.row.col.f32.f16.f16.f32 "
        "{%0,%1,%2,%3}, {%4,%5,%6,%7}, {%8,%9}, {%0,%1,%2,%3};"
        : "+f"(c[0]), "+f"(c[1]), "+f"(c[2]), "+f"(c[3])
        : "r"(a[0]), "r"(a[1]), "r"(a[2]), "r"(a[3]), "r"(b0), "r"(b1));
}
__device__ __forceinline__ void mmai8(int c[4], const uint32_t a[4], uint32_t b0, uint32_t b1) {
    asm volatile(
        "mma.sync.aligned.m16n8k32.row.col.s32.s8.s8.s32 "
        "{%0,%1,%2,%3}, {%4,%5,%6,%7}, {%8,%9}, {%0,%1,%2,%3};"
        : "+r"(c[0]), "+r"(c[1]), "+r"(c[2]), "+r"(c[3])
        : "r"(a[0]), "r"(a[1]), "r"(a[2]), "r"(a[3]), "r"(b0), "r"(b1));
}
#define LDSM4(r, a) \
    asm volatile("ldmatrix.sync.aligned.m8n8.x4.shared.b16 {%0,%1,%2,%3}, [%4];" \
        : "=r"((r)[0]), "=r"((r)[1]), "=r"((r)[2]), "=r"((r)[3]) : "r"(a))

__device__ __forceinline__ void split2h(float v0, float v1, __half2& h, __half2& l) {
    __half h0 = __float2half(v0), h1 = __float2half(v1);
    h.x = h0; h.y = h1;
    l.x = __float2half(v0 - __half2float(h0));
    l.y = __float2half(v1 - __half2float(h1));
}

// ---------------- fp16 GEMM (R8 config: 256 thr, 8 warps 4Mx2N, warp tile 64x64) ----------------
template<bool SPLIT>
__device__ __forceinline__ void issue_tile(
    uint32_t sstage,
    const __half* __restrict__ Ah, const __half* __restrict__ Al,
    const __half* __restrict__ Bh, const __half* __restrict__ Bl,
    int bm, int bn, int K, int k0, int tid)
{
    if (SPLIT) {
        #pragma unroll
        for (int t = 0; t < 12; ++t) {
            const int c = tid + t * 256;
            const __half* src;
            uint32_t off;
            if (c < 2048) {
                const int tile = c >> 10, cc = c & 1023, row = cc >> 2, ch = cc & 3;
                src = (tile ? Al : Ah) + (long long)(bm + row) * K + k0 + ch * 8;
                off = tile * 16384 + row * 64 + ((ch ^ ((row >> 1) & 3)) << 4);
            } else {
                const int c2 = c - 2048, tile = c2 >> 9, cc = c2 & 511, row = cc >> 2, ch = cc & 3;
                src = (tile ? Bl : Bh) + (long long)(bn + row) * K + k0 + ch * 8;
                off = 32768 + tile * 8192 + row * 64 + ((ch ^ ((row >> 1) & 3)) << 4);
            }
            asm volatile("cp.async.cg.shared.global [%0], [%1], 16;"
                         :: "r"(sstage + off), "l"(src));
        }
    } else {
        #pragma unroll
        for (int t = 0; t < 6; ++t) {
            const int c = tid + t * 256;
            const __half* src;
            uint32_t off;
            if (c < 1024) {
                const int row = c >> 2, ch = c & 3;
                src = Ah + (long long)(bm + row) * K + k0 + ch * 8;
                off = row * 64 + ((ch ^ ((row >> 1) & 3)) << 4);
            } else {
                const int c2 = c - 1024, row = c2 >> 2, ch = c2 & 3;
                src = Bh + (long long)(bn + row) * K + k0 + ch * 8;
                off = 16384 + row * 64 + ((ch ^ ((row >> 1) & 3)) << 4);
            }
            asm volatile("cp.async.cg.shared.global [%0], [%1], 16;"
                         :: "r"(sstage + off), "l"(src));
        }
    }
}

template<bool SPLIT, int ACT, bool BIAS, bool OUTF32, bool OUTPAIR, bool OUTH>
__global__ void __launch_bounds__(256, 1)
fp16_gemm(const __half* __restrict__ Ah, const __half* __restrict__ Al,
          const __half* __restrict__ Bh, const __half* __restrict__ Bl,
          const float* __restrict__ bias, float* __restrict__ Cf,
          __half* __restrict__ Ch, __half* __restrict__ Cl,
          int K, int N, float alpha,
          long long sA, long long sB, long long sC, long long sBias)
{
    constexpr uint32_t STAGE_B = SPLIT ? 49152u : 24576u;
    constexpr uint32_t BOFF    = SPLIT ? 32768u : 16384u;
    constexpr int NSTAGE       = SPLIT ? 3 : 4;
    extern __shared__ __align__(16) char smem[];
    Ah += (long long)blockIdx.z * sA;
    Bh += (long long)blockIdx.z * sB;
    if (SPLIT) { Al += (long long)blockIdx.z * sA; Bl += (long long)blockIdx.z * sB; }
    if (BIAS) bias += (long long)blockIdx.z * sBias;
    const int bm = blockIdx.y * 256, bn = blockIdx.x * 128;
    const int tid = threadIdx.x, lane = tid & 31, wid = tid >> 5;
    const int wm = wid & 3, wn = wid >> 2;
    const uint32_t sb = smem_u32(smem);

    const int m1 = (lane >> 3) & 1;
    const int mh = lane >> 4;
    const int lr = lane & 7;

    float acc[4][8][4];
    #pragma unroll
    for (int i = 0; i < 4; i++)
        #pragma unroll
        for (int j = 0; j < 8; j++)
            #pragma unroll
            for (int p = 0; p < 4; p++) acc[i][j][p] = 0.f;

    const int iters = K >> 5;
    #pragma unroll
    for (int s = 0; s < NSTAGE - 1; ++s) {
        issue_tile<SPLIT>(sb + s * STAGE_B, Ah, Al, Bh, Bl, bm, bn, K, s * 32, tid);
        asm volatile("cp.async.commit_group;" ::: "memory");
    }

    for (int t = 0; t < iters; ++t) {
        asm volatile("cp.async.wait_group %0;" :: "n"(NSTAGE - 2) : "memory");
        __syncthreads();
        if (t + NSTAGE - 1 < iters)
            issue_tile<SPLIT>(sb + ((t + NSTAGE - 1) % NSTAGE) * STAGE_B, Ah, Al, Bh, Bl,
                              bm, bn, K, (t + NSTAGE - 1) * 32, tid);
        asm volatile("cp.async.commit_group;" ::: "memory");

        const uint32_t sbase = sb + (t % NSTAGE) * STAGE_B;
        #pragma unroll
        for (int ks = 0; ks < 2; ++ks) {
            uint32_t ah[4][4], al[4][4];
            #pragma unroll
            for (int i = 0; i < 4; ++i) {
                const int rr = wm * 64 + i * 16 + m1 * 8 + lr;
                const int sw = (rr >> 1) & 3;
                const uint32_t addr = sbase + rr * 64 + (uint32_t)(((ks * 2 + mh) ^ sw) << 4);
                LDSM4(ah[i], addr);
                if (SPLIT) LDSM4(al[i], addr + 16384u);
            }
            #pragma unroll
            for (int jp = 0; jp < 4; ++jp) {
                const int rr = wn * 64 + jp * 16 + m1 * 8 + lr;
                const int sw = (rr >> 1) & 3;
                const uint32_t addr = sbase + BOFF + rr * 64 + (uint32_t)(((ks * 2 + mh) ^ sw) << 4);
                uint32_t bh[4], bl[4];
                LDSM4(bh, addr);
                if (SPLIT) LDSM4(bl, addr + 8192u);
                #pragma unroll
                for (int i = 0; i < 4; ++i) {
                    mmafp16(acc[i][jp * 2],     ah[i], bh[0], bh[2]);
                    mmafp16(acc[i][jp * 2 + 1], ah[i], bh[1], bh[3]);
                    if (SPLIT) {
                        mmafp16(acc[i][jp * 2],     ah[i], bl[0], bl[2]);
                        mmafp16(acc[i][jp * 2 + 1], ah[i], bl[1], bl[3]);
                        mmafp16(acc[i][jp * 2],     al[i], bh[0], bh[2]);
                        mmafp16(acc[i][jp * 2 + 1], al[i], bh[1], bh[3]);
                    }
                }
            }
        }
        __syncthreads();
    }

    #pragma unroll
    for (int i = 0; i < 4; ++i) {
        const long long r0 = bm + wm * 64 + i * 16 + (lane >> 2);
        #pragma unroll
        for (int j = 0; j < 8; ++j) {
            const int c0 = bn + wn * 64 + j * 8 + (lane & 3) * 2;
            float v0 = acc[i][j][0] * alpha;
            float v1 = acc[i][j][1] * alpha;
            float v2 = acc[i][j][2] * alpha;
            float v3 = acc[i][j][3] * alpha;
            if (BIAS) {
                float2 bb = *(const float2*)(bias + c0);
                v0 += bb.x; v1 += bb.y; v2 += bb.x; v3 += bb.y;
            }
            if (ACT == 1) {
                v0 = 0.5f * v0 * (1.0f + erff(v0 * 0.7071067811865475f));
                v1 = 0.5f * v1 * (1.0f + erff(v1 * 0.7071067811865475f));
                v2 = 0.5f * v2 * (1.0f + erff(v2 * 0.7071067811865475f));
                v3 = 0.5f * v3 * (1.0f + erff(v3 * 0.7071067811865475f));
            }
            const long long off0 = (long long)blockIdx.z * sC + r0 * N + c0;
            const long long off1 = off0 + 8LL * N;
            if (OUTF32) {
                *(float2*)(Cf + off0) = make_float2(v0, v1);
                *(float2*)(Cf + off1) = make_float2(v2, v3);
            }
            if (OUTPAIR) {
                __half2 h, l;
                split2h(v0, v1, h, l);
                *(__half2*)(Ch + off0) = h;
                *(__half2*)(Cl + off0) = l;
                split2h(v2, v3, h, l);
                *(__half2*)(Ch + off1) = h;
                *(__half2*)(Cl + off1) = l;
            }
            if (OUTH) {
                *(__half2*)(Ch + off0) = __floats2half2_rn(v0, v1);
                *(__half2*)(Ch + off1) = __floats2half2_rn(v2, v3);
            }
        }
    }
}

// ---------------- int8 cross GEMM: C += sA[i]*sB[j]*(A8[i,:]·B8[j,:]), K=1024 ----------------
// block 256x128, BK=64 bytes, 4 stages (24576B each: A 16K | B 8K), 8 warps 4Mx2N.
__device__ __forceinline__ void issue_i8(
    uint32_t sstage, const int8_t* __restrict__ A8, const int8_t* __restrict__ B8,
    int bm, int bn, int K, int k0, int tid)
{
    #pragma unroll
    for (int t = 0; t < 6; ++t) {
        const int c = tid + t * 256;
        const int8_t* src;
        uint32_t off;
        if (c < 1024) {
            const int row = c >> 2, ch = c & 3;
            src = A8 + (long long)(bm + row) * K + k0 + ch * 16;
            off = row * 64 + ((ch ^ ((row >> 1) & 3)) << 4);
        } else {
            const int c2 = c - 1024, row = c2 >> 2, ch = c2 & 3;
            src = B8 + (long long)(bn + row) * K + k0 + ch * 16;
            off = 16384 + row * 64 + ((ch ^ ((row >> 1) & 3)) << 4);
        }
        asm volatile("cp.async.cg.shared.global [%0], [%1], 16;"
                     :: "r"(sstage + off), "l"(src));
    }
}

__global__ void __launch_bounds__(256, 1)
i8_gemm(const int8_t* __restrict__ A8, const int8_t* __restrict__ B8,
        const float* __restrict__ sA, const float* __restrict__ sB,
        float* __restrict__ C, int K, int N,
        long long strA, long long strB, long long strC, int rowsB)
{
    extern __shared__ __align__(16) char smem[];
    A8 += (long long)blockIdx.z * strA;
    B8 += (long long)blockIdx.z * strB;
    C  += (long long)blockIdx.z * strC;
    sA += (long long)blockIdx.z * rowsB;
    sB += (long long)blockIdx.z * rowsB;
    const int bm = blockIdx.y * 256, bn = blockIdx.x * 128;
    const int tid = threadIdx.x, lane = tid & 31, wid = tid >> 5;
    const int wm = wid & 3, wn = wid >> 2;
    const uint32_t sb = smem_u32(smem);
    const int m1 = (lane >> 3) & 1;
    const int mh = lane >> 4;
    const int lr = lane & 7;

    int acc[4][8][4];
    #pragma unroll
    for (int i = 0; i < 4; i++)
        #pragma unroll
        for (int j = 0; j < 8; j++)
            #pragma unroll
            for (int p = 0; p < 4; p++) acc[i][j][p] = 0;

    const int iters = K >> 6;     // 64 bytes per iter
    #pragma unroll
    for (int s = 0; s < 3; ++s) {
        issue_i8(sb + s * 24576u, A8, B8, bm, bn, K, s * 64, tid);
        asm volatile("cp.async.commit_group;" ::: "memory");
    }
    for (int t = 0; t < iters; ++t) {
        asm volatile("cp.async.wait_group 2;" ::: "memory");
        __syncthreads();
        if (t + 3 < iters)
            issue_i8(sb + ((t + 3) & 3) * 24576u, A8, B8, bm, bn, K, (t + 3) * 64, tid);
        asm volatile("cp.async.commit_group;" ::: "memory");

        const uint32_t sbase = sb + (t & 3) * 24576u;
        #pragma unroll
        for (int ks = 0; ks < 2; ++ks) {
            uint32_t a[4][4];
            #pragma unroll
            for (int i = 0; i < 4; ++i) {
                const int rr = wm * 64 + i * 16 + m1 * 8 + lr;
                const int sw = (rr >> 1) & 3;
                LDSM4(a[i], sbase + rr * 64 + (uint32_t)(((ks * 2 + mh) ^ sw) << 4));
            }
            #pragma unroll
            for (int jp = 0; jp < 4; ++jp) {
                const int rr = wn * 64 + jp * 16 + m1 * 8 + lr;
                const int sw = (rr >> 1) & 3;
                uint32_t b[4];
                LDSM4(b, sbase + 16384u + rr * 64 + (uint32_t)(((ks * 2 + mh) ^ sw) << 4));
                #pragma unroll
                for (int i = 0; i < 4; ++i) {
                    mmai8(acc[i][jp * 2],     a[i], b[0], b[2]);
                    mmai8(acc[i][jp * 2 + 1], a[i], b[1], b[3]);
                }
            }
        }
        __syncthreads();
    }

    // epilogue: C += sA[r]*sB[c]*acc
    #pragma unroll
    for (int i = 0; i < 4; ++i) {
        const int r0 = bm + wm * 64 + i * 16 + (lane >> 2);
        const float sa0 = sA[r0], sa1 = sA[r0 + 8];
        #pragma unroll
        for (int j = 0; j < 8; ++j) {
            const int c0 = bn + wn * 64 + j * 8 + (lane & 3) * 2;
            const float2 sbv = *(const float2*)(sB + c0);
            const long long off0 = (long long)r0 * N + c0;
            const long long off1 = off0 + 8LL * N;
            float2 c0v = *(float2*)(C + off0);
            float2 c1v = *(float2*)(C + off1);
            c0v.x += sa0 * sbv.x * (float)acc[i][j][0];
            c0v.y += sa0 * sbv.y * (float)acc[i][j][1];
            c1v.x += sa1 * sbv.x * (float)acc[i][j][2];
            c1v.y += sa1 * sbv.y * (float)acc[i][j][3];
            *(float2*)(C + off0) = c0v;
            *(float2*)(C + off1) = c1v;
        }
    }
}

// ---------------- quantize k/q rows to 2-limb int8 ----------------
// z=0: k -> k8 = [k8h | k8l], sk = s   ; z=1: q -> q8 = [q8l | q8h], sq = s*alpha/2048
__global__ void quant_kq(const __half* __restrict__ kh, const __half* __restrict__ kl,
                         const __half* __restrict__ qh, const __half* __restrict__ ql,
                         int8_t* __restrict__ k8, float* __restrict__ sk,
                         int8_t* __restrict__ q8, float* __restrict__ sq)
{
    const int z = blockIdx.y;
    const int row = blockIdx.x * 8 + (threadIdx.x >> 5);
    const int lane = threadIdx.x & 31;
    const __half* H = z ? qh : kh;
    const __half* L = z ? ql : kl;
    const long long base = (long long)row * DMODEL + lane * 16;

    float h[16], l[16];
    #pragma unroll
    for (int i = 0; i < 8; ++i) {
        __half2 hv = *(const __half2*)(H + base + i * 2);
        __half2 lv = *(const __half2*)(L + base + i * 2);
        h[i * 2] = __half2float(hv.x); h[i * 2 + 1] = __half2float(hv.y);
        l[i * 2] = __half2float(lv.x); l[i * 2 + 1] = __half2float(lv.y);
    }
    float m = 0.f;
    #pragma unroll
    for (int i = 0; i < 16; ++i) m = fmaxf(m, fabsf(h[i]));
    #pragma unroll
    for (int o = 16; o > 0; o >>= 1) m = fmaxf(m, __shfl_xor_sync(0xffffffffu, m, o));
    const float inv = (m > 0.f) ? 127.0f / m : 0.f;
    const float invl = inv * 2048.0f;

    int8_t oh[16], ol[16];
    #pragma unroll
    for (int i = 0; i < 16; ++i) {
        int a = __float2int_rn(h[i] * inv);
        int b = __float2int_rn(l[i] * invl);
        oh[i] = (int8_t)max(-127, min(127, a));
        ol[i] = (int8_t)max(-127, min(127, b));
    }
    int8_t* out = z ? q8 : k8;
    const long long ob = (long long)row * (2 * DMODEL) + lane * 16;
    if (z == 0) {          // [hi | lo]
        *(uint4*)(out + ob)          = *(uint4*)oh;
        *(uint4*)(out + ob + DMODEL) = *(uint4*)ol;
    } else {               // [lo | hi]
        *(uint4*)(out + ob)          = *(uint4*)ol;
        *(uint4*)(out + ob + DMODEL) = *(uint4*)oh;
    }
    if (lane == 0) {
        const float s = (m > 0.f) ? m / 127.0f : 0.f;
        if (z == 0) sk[row] = s;
        else        sq[row] = s * (0.044194173824159216f / 2048.0f);
    }
}

// ---------------- transpose + convert ----------------
template<bool LO>
__global__ void transpose_convert(const float* __restrict__ in,
                                  __half* __restrict__ oh, __half* __restrict__ ol,
                                  int R, int C, long long sIn, long long sOut)
{
    __shared__ float t[32][33];
    in += (long long)blockIdx.z * sIn;
    oh += (long long)blockIdx.z * sOut;
    if (LO) ol += (long long)blockIdx.z * sOut;
    const int c0 = blockIdx.x * 32, r0 = blockIdx.y * 32;
    #pragma unroll
    for (int j = 0; j < 32; j += 8)
        t[threadIdx.y + j][threadIdx.x] =
            in[(long long)(r0 + threadIdx.y + j) * C + c0 + threadIdx.x];
    __syncthreads();
    #pragma unroll
    for (int j = 0; j < 32; j += 8) {
        const float v = t[threadIdx.x][threadIdx.y + j];
        const __half h = __float2half(v);
        const long long o = (long long)(c0 + threadIdx.y + j) * R + r0 + threadIdx.x;
        oh[o] = h;
        if (LO) ol[o] = __float2half(v - __half2float(h));
    }
}

__global__ void transpose_qkv(const float* __restrict__ wk, const float* __restrict__ wq,
                              const float* __restrict__ wv,
                              __half* __restrict__ kqh, __half* __restrict__ kql,
                              __half* __restrict__ vh)
{
    __shared__ float t[32][33];
    const int which = blockIdx.z;
    const float* in = (which == 0) ? wk : (which == 1) ? wq : wv;
    __half* oh = (which == 2) ? vh : kqh + (long long)which * DMODEL * DMODEL;
    __half* ol = (which == 2) ? nullptr : kql + (long long)which * DMODEL * DMODEL;
    const int c0 = blockIdx.x * 32, r0 = blockIdx.y * 32;
    #pragma unroll
    for (int j = 0; j < 32; j += 8)
        t[threadIdx.y + j][threadIdx.x] =
            in[(long long)(r0 + threadIdx.y + j) * DMODEL + c0 + threadIdx.x];
    __syncthreads();
    #pragma unroll
    for (int j = 0; j < 32; j += 8) {
        const float v = t[threadIdx.x][threadIdx.y + j];
        const __half h = __float2half(v);
        const long long o = (long long)(c0 + threadIdx.y + j) * DMODEL + r0 + threadIdx.x;
        oh[o] = h;
        if (ol) ol[o] = __float2half(v - __half2float(h));
    }
}

__global__ void concat_bias(const float* __restrict__ bk, const float* __restrict__ bq,
                            float* __restrict__ o)
{
    const int i = blockIdx.x * 256 + threadIdx.x;
    o[i] = (i < DMODEL) ? bk[i] : bq[i - DMODEL];
}

// ---------------- pos + embedding ----------------
__global__ void pos_kernel(float* __restrict__ tab) {
    const int s = blockIdx.x;
    #pragma unroll
    for (int j = 0; j < 2; ++j) {
        const int d = threadIdx.x + j * 256;
        const float f = powf(10000.0f, -2.0f * (float)d / 512.0f);
        const float ang = (float)s * f;
        tab[s * DMODEL + d] = ((d & 1) == 0) ? sinf(ang) : cosf(ang);
    }
}

__global__ void embed_kernel(const int* __restrict__ seq, const float* __restrict__ emb,
                             const float* __restrict__ tab, float* __restrict__ x,
                             __half* __restrict__ xh, __half* __restrict__ xl)
{
    const int row = blockIdx.x;
    const int s = row & (SEQ - 1);
    const int tok = seq[row];
    const int d0 = threadIdx.x * 4;
    const float sc = 22.627416997969522f;
    float4 e = *(const float4*)(emb + (long long)tok * DMODEL + d0);
    float4 p = *(const float4*)(tab + s * DMODEL + d0);
    float4 o = { (e.x + p.x) * sc, (e.y + p.y) * sc, (e.z + p.z) * sc, (e.w + p.w) * sc };
    const long long base = (long long)row * DMODEL + d0;
    *(float4*)(x + base) = o;
    __half2 h, l;
    split2h(o.x, o.y, h, l);
    *(__half2*)(xh + base) = h;
    *(__half2*)(xl + base) = l;
    split2h(o.z, o.w, h, l);
    *(__half2*)(xh + base + 2) = h;
    *(__half2*)(xl + base + 2) = l;
}

// ---------------- block reductions ----------------
template<int NT>
__device__ __forceinline__ float blockSum(float v, float* sm) {
    #pragma unroll
    for (int o = 16; o > 0; o >>= 1) v += __shfl_xor_sync(0xffffffffu, v, o);
    const int w = threadIdx.x >> 5;
    if ((threadIdx.x & 31) == 0) sm[w] = v;
    __syncthreads();
    if (threadIdx.x < 32) {
        float x = (threadIdx.x < NT / 32) ? sm[threadIdx.x] : 0.f;
        #pragma unroll
        for (int o = NT / 64; o > 0; o >>= 1) x += __shfl_xor_sync(0xffffffffu, x, o);
        if (threadIdx.x == 0) sm[0] = x;
    }
    __syncthreads();
    float r = sm[0];
    __syncthreads();
    return r;
}
template<int NT>
__device__ __forceinline__ float blockMax(float v, float* sm) {
    #pragma unroll
    for (int o = 16; o > 0; o >>= 1) v = fmaxf(v, __shfl_xor_sync(0xffffffffu, v, o));
    const int w = threadIdx.x >> 5;
    if ((threadIdx.x & 31) == 0) sm[w] = v;
    __syncthreads();
    if (threadIdx.x < 32) {
        float x = (threadIdx.x < NT / 32) ? sm[threadIdx.x] : -INFINITY;
        #pragma unroll
        for (int o = NT / 64; o > 0; o >>= 1) x = fmaxf(x, __shfl_xor_sync(0xffffffffu, x, o));
        if (threadIdx.x == 0) sm[0] = x;
    }
    __syncthreads();
    float r = sm[0];
    __syncthreads();
    return r;
}

// ---------------- softmax ----------------
__global__ void softmax_kernel(const float* __restrict__ S, __half* __restrict__ ph)
{
    __shared__ float sm[8];
    const long long base = (long long)blockIdx.x * SEQ;
    const float* row = S + base;
    const int t = threadIdx.x;
    float vals[8];
    float m = -INFINITY;
    #pragma unroll
    for (int i = 0; i < 8; i++) { vals[i] = row[t + i * 256]; m = fmaxf(m, vals[i]); }
    m = blockMax<256>(m, sm);
    float s = 0.f;
    #pragma unroll
    for (int i = 0; i < 8; i++) { vals[i] = expf(vals[i] - m); s += vals[i]; }
    s = blockSum<256>(s, sm);
    const float inv = 1.f / s;
    #pragma unroll
    for (int i = 0; i < 8; i++)
        ph[base + t + i * 256] = __float2half(vals[i] * inv);
}

// ---------------- fused add + LayerNorm ----------------
template<bool H16>
__global__ void add_ln_kernel(const float* __restrict__ a, const float* __restrict__ b,
                              const float* __restrict__ gamma, const float* __restrict__ beta,
                              float* __restrict__ out, __half* __restrict__ oh)
{
    __shared__ float sm[4];
    const long long base = (long long)blockIdx.x * DMODEL;
    const int d0 = threadIdx.x * 4;
    float4 av = *(const float4*)(a + base + d0);
    float4 bv = *(const float4*)(b + base + d0);
    float z[4] = { av.x + bv.x, av.y + bv.y, av.z + bv.z, av.w + bv.w };
    float s = z[0] + z[1] + z[2] + z[3];
    s = blockSum<128>(s, sm);
    const float mu = s * (1.0f / DMODEL);
    float vs = 0.f;
    #pragma unroll
    for (int i = 0; i < 4; i++) { float dz = z[i] - mu; vs += dz * dz; }
    vs = blockSum<128>(vs, sm);
    const float rstd = rsqrtf(vs * (1.0f / DMODEL) + 1e-5f);
    float4 gv = *(const float4*)(gamma + d0);
    float4 bvv = *(const float4*)(beta + d0);
    float4 o;
    o.x = (z[0] - mu) * rstd * gv.x + bvv.x;
    o.y = (z[1] - mu) * rstd * gv.y + bvv.y;
    o.z = (z[2] - mu) * rstd * gv.z + bvv.z;
    o.w = (z[3] - mu) * rstd * gv.w + bvv.w;
    *(float4*)(out + base + d0) = o;
    if (H16) {
        *(__half2*)(oh + base + d0)     = __floats2half2_rn(o.x, o.y);
        *(__half2*)(oh + base + d0 + 2) = __floats2half2_rn(o.z, o.w);
    }
}

// ---------------- launch ----------------
#define SMEM_SPLIT (3 * 49152)   // 147456
#define SMEM_PLAIN (4 * 24576)   // 98304
#define SMEM_I8    (4 * 24576)   // 98304

extern "C" void kernel_launch(void* const* d_in, const int* in_sizes, int n_in,
                              void* d_out, int out_size)
{
    const int*   seq  = (const int*)  d_in[0];
    const float* emb  = (const float*)d_in[1];
    const float* wk   = (const float*)d_in[2];
    const float* bk   = (const float*)d_in[3];
    const float* wq   = (const float*)d_in[4];
    const float* bq   = (const float*)d_in[5];
    const float* wv   = (const float*)d_in[6];
    const float* bv   = (const float*)d_in[7];
    const float* ln_g = (const float*)d_in[8];
    const float* ln_b = (const float*)d_in[9];
    const float* w1   = (const float*)d_in[10];
    const float* b1   = (const float*)d_in[11];
    const float* w2   = (const float*)d_in[12];
    const float* b2   = (const float*)d_in[13];
    float* out = (float*)d_out;

    float *x, *v, *at, *r, *f2, *sc, *pos, *bkq, *sk, *sq;
    __half *xh, *xl, *kqh, *kql, *vTh, *rh, *ph, *f1h;
    __half *wkqTh, *wkqTl, *wvTh, *w1Th, *w2Th;
    int8_t *k8, *q8;
    cudaGetSymbolAddress((void**)&x,     g_x);
    cudaGetSymbolAddress((void**)&v,     g_v);
    cudaGetSymbolAddress((void**)&at,    g_at);
    cudaGetSymbolAddress((void**)&r,     g_r);
    cudaGetSymbolAddress((void**)&f2,    g_f2);
    cudaGetSymbolAddress((void**)&sc,    g_sc);
    cudaGetSymbolAddress((void**)&pos,   g_pos);
    cudaGetSymbolAddress((void**)&bkq,   g_bkq);
    cudaGetSymbolAddress((void**)&sk,    g_sk);
    cudaGetSymbolAddress((void**)&sq,    g_sq);
    cudaGetSymbolAddress((void**)&xh,    g_xh);
    cudaGetSymbolAddress((void**)&xl,    g_xl);
    cudaGetSymbolAddress((void**)&kqh,   g_kqh);
    cudaGetSymbolAddress((void**)&kql,   g_kql);
    cudaGetSymbolAddress((void**)&vTh,   g_vTh);
    cudaGetSymbolAddress((void**)&rh,    g_rh);
    cudaGetSymbolAddress((void**)&ph,    g_ph);
    cudaGetSymbolAddress((void**)&f1h,   g_f1h);
    cudaGetSymbolAddress((void**)&wkqTh, g_wkqTh);
    cudaGetSymbolAddress((void**)&wkqTl, g_wkqTl);
    cudaGetSymbolAddress((void**)&wvTh,  g_wvTh);
    cudaGetSymbolAddress((void**)&w1Th,  g_w1Th);
    cudaGetSymbolAddress((void**)&w2Th,  g_w2Th);
    cudaGetSymbolAddress((void**)&k8,    g_k8);
    cudaGetSymbolAddress((void**)&q8,    g_q8);

    __half* kh = kqh;
    __half* kl = kql;
    __half* qh = kqh + (long long)BSTOT * DMODEL;
    __half* ql = kql + (long long)BSTOT * DMODEL;

    cudaFuncSetAttribute(fp16_gemm<true,  0, true,  false, true,  false>, cudaFuncAttributeMaxDynamicSharedMemorySize, SMEM_SPLIT);
    cudaFuncSetAttribute(fp16_gemm<false, 0, true,  true,  false, false>, cudaFuncAttributeMaxDynamicSharedMemorySize, SMEM_PLAIN);
    cudaFuncSetAttribute(fp16_gemm<false, 0, false, true,  false, false>, cudaFuncAttributeMaxDynamicSharedMemorySize, SMEM_PLAIN);
    cudaFuncSetAttribute(fp16_gemm<false, 1, true,  false, false, true >, cudaFuncAttributeMaxDynamicSharedMemorySize, SMEM_PLAIN);
    cudaFuncSetAttribute(i8_gemm, cudaFuncAttributeMaxDynamicSharedMemorySize, SMEM_I8);

    dim3 tb(32, 8);

    pos_kernel<<<SEQ, 256>>>(pos);
    embed_kernel<<<BSTOT, 128>>>(seq, emb, pos, x, xh, xl);
    concat_bias<<<4, 256>>>(bk, bq, bkq);
    transpose_qkv<<<dim3(16, 16, 3), tb>>>(wk, wq, wv, wkqTh, wkqTl, wvTh);

    // fused k+q projection (split fp16, z=2)
    fp16_gemm<true, 0, true, false, true, false><<<dim3(4, 32, 2), 256, SMEM_SPLIT>>>(
        xh, xl, wkqTh, wkqTl, bkq, nullptr, kqh, kql, DMODEL, DMODEL, 1.f,
        0, (long long)DMODEL * DMODEL, (long long)BSTOT * DMODEL, DMODEL);
    // v projection (plain)
    fp16_gemm<false, 0, true, true, false, false><<<dim3(4, 32, 1), 256, SMEM_PLAIN>>>(
        xh, nullptr, wvTh, nullptr, bv, v, nullptr, nullptr, DMODEL, DMODEL, 1.f, 0, 0, 0, 0);

    // quantize k,q to 2-limb int8 (rowwise, tied scales)
    quant_kq<<<dim3(BSTOT / 8, 2), 256>>>(kh, kl, qh, ql, k8, sk, q8, sq);

    transpose_convert<false><<<dim3(64, 16, 1), tb>>>(w1, w1Th, nullptr, DMODEL, DFFN, 0, 0);
    transpose_convert<false><<<dim3(16, 64, 1), tb>>>(w2, w2Th, nullptr, DFFN, DMODEL, 0, 0);
    transpose_convert<false><<<dim3(16, 64, NBATCH), tb>>>(v, vTh, nullptr, SEQ, DMODEL,
        (long long)SEQ * DMODEL, (long long)DMODEL * SEQ);

    // scores hi: alpha * kh @ qh^T  (plain fp16 — operands exact)
    fp16_gemm<false, 0, false, true, false, false><<<dim3(16, 8, NBATCH), 256, SMEM_PLAIN>>>(
        kh, nullptr, qh, nullptr, nullptr, sc, nullptr, nullptr, DMODEL, SEQ,
        0.044194173824159216f,
        (long long)SEQ * DMODEL, (long long)SEQ * DMODEL, (long long)SEQ * SEQ, 0);

    // scores cross: sc += sk[i]*sq[j]*( [k8h|k8l]·[q8l|q8h] )  (int8 k32, K=1024)
    i8_gemm<<<dim3(16, 8, NBATCH), 256, SMEM_I8>>>(
        k8, q8, sk, sq, sc, 2 * DMODEL, SEQ,
        (long long)SEQ * 2 * DMODEL, (long long)SEQ * 2 * DMODEL,
        (long long)SEQ * SEQ, SEQ);

    softmax_kernel<<<NBATCH * SEQ, 256>>>(sc, ph);

    // attn = P @ V (plain fp16)
    fp16_gemm<false, 0, false, true, false, false><<<dim3(4, 8, NBATCH), 256, SMEM_PLAIN>>>(
        ph, nullptr, vTh, nullptr, nullptr, at, nullptr, nullptr, SEQ, DMODEL, 1.f,
        (long long)SEQ * SEQ, (long long)DMODEL * SEQ, (long long)SEQ * DMODEL, 0);

    add_ln_kernel<true><<<BSTOT, 128>>>(x, at, ln_g, ln_b, r, rh);

    // FFN (plain fp16)
    fp16_gemm<false, 1, true, false, false, true><<<dim3(16, 32, 1), 256, SMEM_PLAIN>>>(
        rh, nullptr, w1Th, nullptr, b1, nullptr, f1h, nullptr, DMODEL, DFFN, 1.f, 0, 0, 0, 0);
    fp16_gemm<false, 0, true, true, false, false><<<dim3(4, 32, 1), 256, SMEM_PLAIN>>>(
        f1h, nullptr, w2Th, nullptr, b2, f2, nullptr, nullptr, DFFN, DMODEL, 1.f, 0, 0, 0, 0);

    add_ln_kernel<false><<<BSTOT, 128>>>(r, f2, ln_g, ln_b, out, nullptr);
}

// round 12
// speedup vs baseline: 1.4307x; 1.4307x over previous
#include <cuda_runtime.h>
#include <cuda_fp16.h>
#include <cstdint>
#include <math.h>

#define NBATCH 4
#define SEQ    2048
#define DMODEL 512
#define DFFN   2048
#define BSTOT  (NBATCH*SEQ)

// ---------------- scratch ----------------
__device__ __align__(256) float g_x [BSTOT*DMODEL];
__device__ __align__(256) float g_v [BSTOT*DMODEL];
__device__ __align__(256) float g_at[BSTOT*DMODEL];
__device__ __align__(256) float g_r [BSTOT*DMODEL];
__device__ __align__(256) float g_f2[BSTOT*DMODEL];
__device__ __align__(256) float g_sc[(long long)NBATCH*SEQ*SEQ];
__device__ __align__(256) float g_pos[SEQ*DMODEL];
__device__ __align__(256) float g_bkq[2*DMODEL];

__device__ __align__(256) __half g_xh[BSTOT*DMODEL];
__device__ __align__(256) __half g_xl[BSTOT*DMODEL];
__device__ __align__(256) __half g_kqh[2*BSTOT*DMODEL];
__device__ __align__(256) __half g_kql[2*BSTOT*DMODEL];
__device__ __align__(256) __half g_vTh[BSTOT*DMODEL];
__device__ __align__(256) __half g_rh[BSTOT*DMODEL];
__device__ __align__(256) __half g_ph[(long long)NBATCH*SEQ*SEQ];
__device__ __align__(256) __half g_f1h[(long long)BSTOT*DFFN];
__device__ __align__(256) __half g_wkqTh[2*DMODEL*DMODEL];
__device__ __align__(256) __half g_wkqTl[2*DMODEL*DMODEL];
__device__ __align__(256) __half g_wvTh[DMODEL*DMODEL];
__device__ __align__(256) __half g_w1Th[DFFN*DMODEL];
__device__ __align__(256) __half g_w2Th[DMODEL*DFFN];

// ---------------- helpers ----------------
__device__ __forceinline__ uint32_t smem_u32(const void* p) {
    uint32_t a;
    asm("{ .reg .u64 t; cvta.to.shared.u64 t, %1; cvt.u32.u64 %0, t; }" : "=r"(a) : "l"(p));
    return a;
}
__device__ __forceinline__ void mmafp16(float c[4], const uint32_t a[4], uint32_t b0, uint32_t b1) {
    asm volatile(
        "mma.sync.aligned.m16n8k16.row.col.f32.f16.f16.f32 "
        "{%0,%1,%2,%3}, {%4,%5,%6,%7}, {%8,%9}, {%0,%1,%2,%3};"
        : "+f"(c[0]), "+f"(c[1]), "+f"(c[2]), "+f"(c[3])
        : "r"(a[0]), "r"(a[1]), "r"(a[2]), "r"(a[3]), "r"(b0), "r"(b1));
}
#define LDSM4(r, a) \
    asm volatile("ldmatrix.sync.aligned.m8n8.x4.shared.b16 {%0,%1,%2,%3}, [%4];" \
        : "=r"((r)[0]), "=r"((r)[1]), "=r"((r)[2]), "=r"((r)[3]) : "r"(a))

__device__ __forceinline__ void split2h(float v0, float v1, __half2& h, __half2& l) {
    __half h0 = __float2half(v0), h1 = __float2half(v1);
    h.x = h0; h.y = h1;
    l.x = __float2half(v0 - __half2float(h0));
    l.y = __float2half(v1 - __half2float(h1));
}

// ---------------- fp16 GEMM (optionally 3-term split) ----------------
// C[M,N] = act(alpha*(A@B^T) + bias); A [M,K] K-major, B [N,K] K-major (+lo if SPLIT)
// block 256x128, BK=32, 256 threads, 8 warps (4M x 2N), warp tile 64x64, 4-stage cp.async.
// SMEM stage split: Ah 16K | Al 16K | Bh 8K | Bl 8K = 48K ; plain: Ah 16K | Bh 8K = 24K

template<bool SPLIT>
__device__ __forceinline__ void issue_tile(
    uint32_t sstage,
    const __half* __restrict__ Ah, const __half* __restrict__ Al,
    const __half* __restrict__ Bh, const __half* __restrict__ Bl,
    int bm, int bn, int K, int k0, int tid)
{
    if (SPLIT) {
        #pragma unroll
        for (int t = 0; t < 12; ++t) {
            const int c = tid + t * 256;
            const __half* src;
            uint32_t off;
            if (c < 2048) {
                const int tile = c >> 10, cc = c & 1023, row = cc >> 2, ch = cc & 3;
                src = (tile ? Al : Ah) + (long long)(bm + row) * K + k0 + ch * 8;
                off = tile * 16384 + row * 64 + ((ch ^ ((row >> 1) & 3)) << 4);
            } else {
                const int c2 = c - 2048, tile = c2 >> 9, cc = c2 & 511, row = cc >> 2, ch = cc & 3;
                src = (tile ? Bl : Bh) + (long long)(bn + row) * K + k0 + ch * 8;
                off = 32768 + tile * 8192 + row * 64 + ((ch ^ ((row >> 1) & 3)) << 4);
            }
            asm volatile("cp.async.cg.shared.global [%0], [%1], 16;"
                         :: "r"(sstage + off), "l"(src));
        }
    } else {
        #pragma unroll
        for (int t = 0; t < 6; ++t) {
            const int c = tid + t * 256;
            const __half* src;
            uint32_t off;
            if (c < 1024) {
                const int row = c >> 2, ch = c & 3;
                src = Ah + (long long)(bm + row) * K + k0 + ch * 8;
                off = row * 64 + ((ch ^ ((row >> 1) & 3)) << 4);
            } else {
                const int c2 = c - 1024, row = c2 >> 2, ch = c2 & 3;
                src = Bh + (long long)(bn + row) * K + k0 + ch * 8;
                off = 16384 + row * 64 + ((ch ^ ((row >> 1) & 3)) << 4);
            }
            asm volatile("cp.async.cg.shared.global [%0], [%1], 16;"
                         :: "r"(sstage + off), "l"(src));
        }
    }
}

template<bool SPLIT, int ACT, bool BIAS, bool OUTF32, bool OUTPAIR, bool OUTH>
__global__ void __launch_bounds__(256, 1)
fp16_gemm(const __half* __restrict__ Ah, const __half* __restrict__ Al,
          const __half* __restrict__ Bh, const __half* __restrict__ Bl,
          const float* __restrict__ bias, float* __restrict__ Cf,
          __half* __restrict__ Ch, __half* __restrict__ Cl,
          int K, int N, float alpha,
          long long sA, long long sB, long long sC, long long sBias)
{
    constexpr uint32_t STAGE_B = SPLIT ? 49152u : 24576u;
    constexpr uint32_t BOFF    = SPLIT ? 32768u : 16384u;
    constexpr int NSTAGE       = 4;
    extern __shared__ __align__(16) char smem[];
    Ah += (long long)blockIdx.z * sA;
    Bh += (long long)blockIdx.z * sB;
    if (SPLIT) { Al += (long long)blockIdx.z * sA; Bl += (long long)blockIdx.z * sB; }
    if (BIAS) bias += (long long)blockIdx.z * sBias;
    const int bm = blockIdx.y * 256, bn = blockIdx.x * 128;
    const int tid = threadIdx.x, lane = tid & 31, wid = tid >> 5;
    const int wm = wid & 3, wn = wid >> 2;
    const uint32_t sb = smem_u32(smem);

    const int m1 = (lane >> 3) & 1;
    const int mh = lane >> 4;
    const int lr = lane & 7;

    float acc[4][8][4];
    #pragma unroll
    for (int i = 0; i < 4; i++)
        #pragma unroll
        for (int j = 0; j < 8; j++)
            #pragma unroll
            for (int p = 0; p < 4; p++) acc[i][j][p] = 0.f;

    const int iters = K >> 5;
    #pragma unroll
    for (int s = 0; s < NSTAGE - 1; ++s) {
        issue_tile<SPLIT>(sb + s * STAGE_B, Ah, Al, Bh, Bl, bm, bn, K, s * 32, tid);
        asm volatile("cp.async.commit_group;" ::: "memory");
    }

    for (int t = 0; t < iters; ++t) {
        asm volatile("cp.async.wait_group %0;" :: "n"(NSTAGE - 2) : "memory");
        __syncthreads();
        if (t + NSTAGE - 1 < iters)
            issue_tile<SPLIT>(sb + ((t + NSTAGE - 1) % NSTAGE) * STAGE_B, Ah, Al, Bh, Bl,
                              bm, bn, K, (t + NSTAGE - 1) * 32, tid);
        asm volatile("cp.async.commit_group;" ::: "memory");

        const uint32_t sbase = sb + (t % NSTAGE) * STAGE_B;
        #pragma unroll
        for (int ks = 0; ks < 2; ++ks) {
            uint32_t ah[4][4], al[4][4];
            #pragma unroll
            for (int i = 0; i < 4; ++i) {
                const int rr = wm * 64 + i * 16 + m1 * 8 + lr;
                const int sw = (rr >> 1) & 3;
                const uint32_t addr = sbase + rr * 64 + (uint32_t)(((ks * 2 + mh) ^ sw) << 4);
                LDSM4(ah[i], addr);
                if (SPLIT) LDSM4(al[i], addr + 16384u);
            }
            #pragma unroll
            for (int jp = 0; jp < 4; ++jp) {
                const int rr = wn * 64 + jp * 16 + m1 * 8 + lr;
                const int sw = (rr >> 1) & 3;
                const uint32_t addr = sbase + BOFF + rr * 64 + (uint32_t)(((ks * 2 + mh) ^ sw) << 4);
                uint32_t bh[4], bl[4];
                LDSM4(bh, addr);
                if (SPLIT) LDSM4(bl, addr + 8192u);
                #pragma unroll
                for (int i = 0; i < 4; ++i) {
                    mmafp16(acc[i][jp * 2],     ah[i], bh[0], bh[2]);
                    mmafp16(acc[i][jp * 2 + 1], ah[i], bh[1], bh[3]);
                    if (SPLIT) {
                        mmafp16(acc[i][jp * 2],     ah[i], bl[0], bl[2]);
                        mmafp16(acc[i][jp * 2 + 1], ah[i], bl[1], bl[3]);
                        mmafp16(acc[i][jp * 2],     al[i], bh[0], bh[2]);
                        mmafp16(acc[i][jp * 2 + 1], al[i], bh[1], bh[3]);
                    }
                }
            }
        }
        __syncthreads();
    }

    // ---------------- epilogue ----------------
    #pragma unroll
    for (int i = 0; i < 4; ++i) {
        const long long r0 = bm + wm * 64 + i * 16 + (lane >> 2);
        #pragma unroll
        for (int j = 0; j < 8; ++j) {
            const int c0 = bn + wn * 64 + j * 8 + (lane & 3) * 2;
            float v0 = acc[i][j][0] * alpha;
            float v1 = acc[i][j][1] * alpha;
            float v2 = acc[i][j][2] * alpha;
            float v3 = acc[i][j][3] * alpha;
            if (BIAS) {
                float2 bb = *(const float2*)(bias + c0);
                v0 += bb.x; v1 += bb.y; v2 += bb.x; v3 += bb.y;
            }
            if (ACT == 1) {
                v0 = 0.5f * v0 * (1.0f + erff(v0 * 0.7071067811865475f));
                v1 = 0.5f * v1 * (1.0f + erff(v1 * 0.7071067811865475f));
                v2 = 0.5f * v2 * (1.0f + erff(v2 * 0.7071067811865475f));
                v3 = 0.5f * v3 * (1.0f + erff(v3 * 0.7071067811865475f));
            }
            const long long off0 = (long long)blockIdx.z * sC + r0 * N + c0;
            const long long off1 = off0 + 8LL * N;
            if (OUTF32) {
                *(float2*)(Cf + off0) = make_float2(v0, v1);
                *(float2*)(Cf + off1) = make_float2(v2, v3);
            }
            if (OUTPAIR) {
                __half2 h, l;
                split2h(v0, v1, h, l);
                *(__half2*)(Ch + off0) = h;
                *(__half2*)(Cl + off0) = l;
                split2h(v2, v3, h, l);
                *(__half2*)(Ch + off1) = h;
                *(__half2*)(Cl + off1) = l;
            }
            if (OUTH) {
                *(__half2*)(Ch + off0) = __floats2half2_rn(v0, v1);
                *(__half2*)(Ch + off1) = __floats2half2_rn(v2, v3);
            }
        }
    }
}

// ---------------- transpose + convert ----------------
template<bool LO>
__global__ void transpose_convert(const float* __restrict__ in,
                                  __half* __restrict__ oh, __half* __restrict__ ol,
                                  int R, int C, long long sIn, long long sOut)
{
    __shared__ float t[32][33];
    in += (long long)blockIdx.z * sIn;
    oh += (long long)blockIdx.z * sOut;
    if (LO) ol += (long long)blockIdx.z * sOut;
    const int c0 = blockIdx.x * 32, r0 = blockIdx.y * 32;
    #pragma unroll
    for (int j = 0; j < 32; j += 8)
        t[threadIdx.y + j][threadIdx.x] =
            in[(long long)(r0 + threadIdx.y + j) * C + c0 + threadIdx.x];
    __syncthreads();
    #pragma unroll
    for (int j = 0; j < 32; j += 8) {
        const float v = t[threadIdx.x][threadIdx.y + j];
        const __half h = __float2half(v);
        const long long o = (long long)(c0 + threadIdx.y + j) * R + r0 + threadIdx.x;
        oh[o] = h;
        if (LO) ol[o] = __float2half(v - __half2float(h));
    }
}

__global__ void transpose_qkv(const float* __restrict__ wk, const float* __restrict__ wq,
                              const float* __restrict__ wv,
                              __half* __restrict__ kqh, __half* __restrict__ kql,
                              __half* __restrict__ vh)
{
    __shared__ float t[32][33];
    const int which = blockIdx.z;
    const float* in = (which == 0) ? wk : (which == 1) ? wq : wv;
    __half* oh = (which == 2) ? vh : kqh + (long long)which * DMODEL * DMODEL;
    __half* ol = (which == 2) ? nullptr : kql + (long long)which * DMODEL * DMODEL;
    const int c0 = blockIdx.x * 32, r0 = blockIdx.y * 32;
    #pragma unroll
    for (int j = 0; j < 32; j += 8)
        t[threadIdx.y + j][threadIdx.x] =
            in[(long long)(r0 + threadIdx.y + j) * DMODEL + c0 + threadIdx.x];
    __syncthreads();
    #pragma unroll
    for (int j = 0; j < 32; j += 8) {
        const float v = t[threadIdx.x][threadIdx.y + j];
        const __half h = __float2half(v);
        const long long o = (long long)(c0 + threadIdx.y + j) * DMODEL + r0 + threadIdx.x;
        oh[o] = h;
        if (ol) ol[o] = __float2half(v - __half2float(h));
    }
}

__global__ void concat_bias(const float* __restrict__ bk, const float* __restrict__ bq,
                            float* __restrict__ o)
{
    const int i = blockIdx.x * 256 + threadIdx.x;
    o[i] = (i < DMODEL) ? bk[i] : bq[i - DMODEL];
}

// ---------------- pos + embedding ----------------
__global__ void pos_kernel(float* __restrict__ tab) {
    const int s = blockIdx.x;
    #pragma unroll
    for (int j = 0; j < 2; ++j) {
        const int d = threadIdx.x + j * 256;
        const float f = powf(10000.0f, -2.0f * (float)d / 512.0f);
        const float ang = (float)s * f;
        tab[s * DMODEL + d] = ((d & 1) == 0) ? sinf(ang) : cosf(ang);
    }
}

__global__ void embed_kernel(const int* __restrict__ seq, const float* __restrict__ emb,
                             const float* __restrict__ tab, float* __restrict__ x,
                             __half* __restrict__ xh, __half* __restrict__ xl)
{
    const int row = blockIdx.x;
    const int s = row & (SEQ - 1);
    const int tok = seq[row];
    const int d0 = threadIdx.x * 4;
    const float sc = 22.627416997969522f;
    float4 e = *(const float4*)(emb + (long long)tok * DMODEL + d0);
    float4 p = *(const float4*)(tab + s * DMODEL + d0);
    float4 o = { (e.x + p.x) * sc, (e.y + p.y) * sc, (e.z + p.z) * sc, (e.w + p.w) * sc };
    const long long base = (long long)row * DMODEL + d0;
    *(float4*)(x + base) = o;
    __half2 h, l;
    split2h(o.x, o.y, h, l);
    *(__half2*)(xh + base) = h;
    *(__half2*)(xl + base) = l;
    split2h(o.z, o.w, h, l);
    *(__half2*)(xh + base + 2) = h;
    *(__half2*)(xl + base + 2) = l;
}

// ---------------- block reductions ----------------
template<int NT>
__device__ __forceinline__ float blockSum(float v, float* sm) {
    #pragma unroll
    for (int o = 16; o > 0; o >>= 1) v += __shfl_xor_sync(0xffffffffu, v, o);
    const int w = threadIdx.x >> 5;
    if ((threadIdx.x & 31) == 0) sm[w] = v;
    __syncthreads();
    if (threadIdx.x < 32) {
        float x = (threadIdx.x < NT / 32) ? sm[threadIdx.x] : 0.f;
        #pragma unroll
        for (int o = NT / 64; o > 0; o >>= 1) x += __shfl_xor_sync(0xffffffffu, x, o);
        if (threadIdx.x == 0) sm[0] = x;
    }
    __syncthreads();
    float r = sm[0];
    __syncthreads();
    return r;
}
template<int NT>
__device__ __forceinline__ float blockMax(float v, float* sm) {
    #pragma unroll
    for (int o = 16; o > 0; o >>= 1) v = fmaxf(v, __shfl_xor_sync(0xffffffffu, v, o));
    const int w = threadIdx.x >> 5;
    if ((threadIdx.x & 31) == 0) sm[w] = v;
    __syncthreads();
    if (threadIdx.x < 32) {
        float x = (threadIdx.x < NT / 32) ? sm[threadIdx.x] : -INFINITY;
        #pragma unroll
        for (int o = NT / 64; o > 0; o >>= 1) x = fmaxf(x, __shfl_xor_sync(0xffffffffu, x, o));
        if (threadIdx.x == 0) sm[0] = x;
    }
    __syncthreads();
    float r = sm[0];
    __syncthreads();
    return r;
}

// ---------------- softmax (fp32 in, fp16 out) ----------------
__global__ void softmax_kernel(const float* __restrict__ S, __half* __restrict__ ph)
{
    __shared__ float sm[8];
    const long long base = (long long)blockIdx.x * SEQ;
    const float* row = S + base;
    const int t = threadIdx.x;
    float vals[8];
    float m = -INFINITY;
    #pragma unroll
    for (int i = 0; i < 8; i++) { vals[i] = row[t + i * 256]; m = fmaxf(m, vals[i]); }
    m = blockMax<256>(m, sm);
    float s = 0.f;
    #pragma unroll
    for (int i = 0; i < 8; i++) { vals[i] = expf(vals[i] - m); s += vals[i]; }
    s = blockSum<256>(s, sm);
    const float inv = 1.f / s;
    #pragma unroll
    for (int i = 0; i < 8; i++)
        ph[base + t + i * 256] = __float2half(vals[i] * inv);
}

// ---------------- fused add + LayerNorm ----------------
template<bool H16>
__global__ void add_ln_kernel(const float* __restrict__ a, const float* __restrict__ b,
                              const float* __restrict__ gamma, const float* __restrict__ beta,
                              float* __restrict__ out, __half* __restrict__ oh)
{
    __shared__ float sm[4];
    const long long base = (long long)blockIdx.x * DMODEL;
    const int d0 = threadIdx.x * 4;
    float4 av = *(const float4*)(a + base + d0);
    float4 bv = *(const float4*)(b + base + d0);
    float z[4] = { av.x + bv.x, av.y + bv.y, av.z + bv.z, av.w + bv.w };
    float s = z[0] + z[1] + z[2] + z[3];
    s = blockSum<128>(s, sm);
    const float mu = s * (1.0f / DMODEL);
    float vs = 0.f;
    #pragma unroll
    for (int i = 0; i < 4; i++) { float dz = z[i] - mu; vs += dz * dz; }
    vs = blockSum<128>(vs, sm);
    const float rstd = rsqrtf(vs * (1.0f / DMODEL) + 1e-5f);
    float4 gv = *(const float4*)(gamma + d0);
    float4 bvv = *(const float4*)(beta + d0);
    float4 o;
    o.x = (z[0] - mu) * rstd * gv.x + bvv.x;
    o.y = (z[1] - mu) * rstd * gv.y + bvv.y;
    o.z = (z[2] - mu) * rstd * gv.z + bvv.z;
    o.w = (z[3] - mu) * rstd * gv.w + bvv.w;
    *(float4*)(out + base + d0) = o;
    if (H16) {
        *(__half2*)(oh + base + d0)     = __floats2half2_rn(o.x, o.y);
        *(__half2*)(oh + base + d0 + 2) = __floats2half2_rn(o.z, o.w);
    }
}

// ---------------- launch ----------------
#define SMEM_SPLIT (4 * 49152)   // 196608
#define SMEM_PLAIN (4 * 24576)   // 98304

extern "C" void kernel_launch(void* const* d_in, const int* in_sizes, int n_in,
                              void* d_out, int out_size)
{
    const int*   seq  = (const int*)  d_in[0];
    const float* emb  = (const float*)d_in[1];
    const float* wk   = (const float*)d_in[2];
    const float* bk   = (const float*)d_in[3];
    const float* wq   = (const float*)d_in[4];
    const float* bq   = (const float*)d_in[5];
    const float* wv   = (const float*)d_in[6];
    const float* bv   = (const float*)d_in[7];
    const float* ln_g = (const float*)d_in[8];
    const float* ln_b = (const float*)d_in[9];
    const float* w1   = (const float*)d_in[10];
    const float* b1   = (const float*)d_in[11];
    const float* w2   = (const float*)d_in[12];
    const float* b2   = (const float*)d_in[13];
    float* out = (float*)d_out;

    float *x, *v, *at, *r, *f2, *sc, *pos, *bkq;
    __half *xh, *xl, *kqh, *kql, *vTh, *rh, *ph, *f1h;
    __half *wkqTh, *wkqTl, *wvTh, *w1Th, *w2Th;
    cudaGetSymbolAddress((void**)&x,     g_x);
    cudaGetSymbolAddress((void**)&v,     g_v);
    cudaGetSymbolAddress((void**)&at,    g_at);
    cudaGetSymbolAddress((void**)&r,     g_r);
    cudaGetSymbolAddress((void**)&f2,    g_f2);
    cudaGetSymbolAddress((void**)&sc,    g_sc);
    cudaGetSymbolAddress((void**)&pos,   g_pos);
    cudaGetSymbolAddress((void**)&bkq,   g_bkq);
    cudaGetSymbolAddress((void**)&xh,    g_xh);
    cudaGetSymbolAddress((void**)&xl,    g_xl);
    cudaGetSymbolAddress((void**)&kqh,   g_kqh);
    cudaGetSymbolAddress((void**)&kql,   g_kql);
    cudaGetSymbolAddress((void**)&vTh,   g_vTh);
    cudaGetSymbolAddress((void**)&rh,    g_rh);
    cudaGetSymbolAddress((void**)&ph,    g_ph);
    cudaGetSymbolAddress((void**)&f1h,   g_f1h);
    cudaGetSymbolAddress((void**)&wkqTh, g_wkqTh);
    cudaGetSymbolAddress((void**)&wkqTl, g_wkqTl);
    cudaGetSymbolAddress((void**)&wvTh,  g_wvTh);
    cudaGetSymbolAddress((void**)&w1Th,  g_w1Th);
    cudaGetSymbolAddress((void**)&w2Th,  g_w2Th);

    __half* kh = kqh;
    __half* kl = kql;
    __half* qh = kqh + (long long)BSTOT * DMODEL;
    __half* ql = kql + (long long)BSTOT * DMODEL;

    cudaFuncSetAttribute(fp16_gemm<true,  0, true,  false, true,  false>, cudaFuncAttributeMaxDynamicSharedMemorySize, SMEM_SPLIT);
    cudaFuncSetAttribute(fp16_gemm<true,  0, false, true,  false, false>, cudaFuncAttributeMaxDynamicSharedMemorySize, SMEM_SPLIT);
    cudaFuncSetAttribute(fp16_gemm<false, 0, true,  true,  false, false>, cudaFuncAttributeMaxDynamicSharedMemorySize, SMEM_PLAIN);
    cudaFuncSetAttribute(fp16_gemm<false, 0, false, true,  false, false>, cudaFuncAttributeMaxDynamicSharedMemorySize, SMEM_PLAIN);
    cudaFuncSetAttribute(fp16_gemm<false, 1, true,  false, false, true >, cudaFuncAttributeMaxDynamicSharedMemorySize, SMEM_PLAIN);

    dim3 tb(32, 8);

    pos_kernel<<<SEQ, 256>>>(pos);
    embed_kernel<<<BSTOT, 128>>>(seq, emb, pos, x, xh, xl);
    concat_bias<<<4, 256>>>(bk, bq, bkq);
    transpose_qkv<<<dim3(16, 16, 3), tb>>>(wk, wq, wv, wkqTh, wkqTl, wvTh);

    // fused k+q projection (SPLIT, z=2)
    fp16_gemm<true, 0, true, false, true, false><<<dim3(4, 32, 2), 256, SMEM_SPLIT>>>(
        xh, xl, wkqTh, wkqTl, bkq, nullptr, kqh, kql, DMODEL, DMODEL, 1.f,
        0, (long long)DMODEL * DMODEL, (long long)BSTOT * DMODEL, DMODEL);
    // v projection (plain)
    fp16_gemm<false, 0, true, true, false, false><<<dim3(4, 32, 1), 256, SMEM_PLAIN>>>(
        xh, nullptr, wvTh, nullptr, bv, v, nullptr, nullptr, DMODEL, DMODEL, 1.f, 0, 0, 0, 0);

    transpose_convert<false><<<dim3(64, 16, 1), tb>>>(w1, w1Th, nullptr, DMODEL, DFFN, 0, 0);
    transpose_convert<false><<<dim3(16, 64, 1), tb>>>(w2, w2Th, nullptr, DFFN, DMODEL, 0, 0);
    transpose_convert<false><<<dim3(16, 64, NBATCH), tb>>>(v, vTh, nullptr, SEQ, DMODEL,
        (long long)SEQ * DMODEL, (long long)DMODEL * SEQ);

    // scores = k @ q^T / sqrt(D)  (SPLIT)
    fp16_gemm<true, 0, false, true, false, false><<<dim3(16, 8, NBATCH), 256, SMEM_SPLIT>>>(
        kh, kl, qh, ql, nullptr, sc, nullptr, nullptr, DMODEL, SEQ, 0.044194173824159216f,
        (long long)SEQ * DMODEL, (long long)SEQ * DMODEL, (long long)SEQ * SEQ, 0);

    softmax_kernel<<<NBATCH * SEQ, 256>>>(sc, ph);

    // attn = P @ V  (plain fp16)
    fp16_gemm<false, 0, false, true, false, false><<<dim3(4, 8, NBATCH), 256, SMEM_PLAIN>>>(
        ph, nullptr, vTh, nullptr, nullptr, at, nullptr, nullptr, SEQ, DMODEL, 1.f,
        (long long)SEQ * SEQ, (long long)DMODEL * SEQ, (long long)SEQ * DMODEL, 0);

    add_ln_kernel<true><<<BSTOT, 128>>>(x, at, ln_g, ln_b, r, rh);

    // FFN (plain fp16)
    fp16_gemm<false, 1, true, false, false, true><<<dim3(16, 32, 1), 256, SMEM_PLAIN>>>(
        rh, nullptr, w1Th, nullptr, b1, nullptr, f1h, nullptr, DMODEL, DFFN, 1.f, 0, 0, 0, 0);
    fp16_gemm<false, 0, true, true, false, false><<<dim3(4, 32, 1), 256, SMEM_PLAIN>>>(
        f1h, nullptr, w2Th, nullptr, b2, f2, nullptr, nullptr, DFFN, DMODEL, 1.f, 0, 0, 0, 0);

    add_ln_kernel<false><<<BSTOT, 128>>>(r, f2, ln_g, ln_b, out, nullptr);
}